// round 10
// baseline (speedup 1.0000x reference)
#include <cuda_runtime.h>
#include <cstdint>

// ---------------------------------------------------------------------------
// Window-based self-attention (Swin-style), B=64, 56x56, C=128, WS=7, NH=8.
// Round 10: out-projection fused into the attention kernel (one block per
// window, 512 threads). Pipeline is now 3 launches:
//   K0: transpose weights -> g_wT
//   K2: fused LN + window partition + QKV GEMM (tf32 mma) -> g_qkv
//   K3: fused attention (tf32 mma) + out-proj + window merge -> d_out
// ---------------------------------------------------------------------------

#define NTOK      200704            // 4096 windows * 49 tokens
#define CDIM      128
#define QKV_STRIDE 25690112         // NTOK * CDIM
#define SCALE_ATT 0.25f             // HD^-0.5, HD=16
#define LN_EPS    1e-5f
#define SMEM_LDA  132               // padded row stride (floats)

__device__ float g_qkv[(size_t)3 * NTOK * CDIM];     // ~308 MB
__device__ float g_wT[384 * 128 + 128 * 128];        // transposed w_qkv | w_out

// ---------------------------------------------------------------------------
// helpers
// ---------------------------------------------------------------------------
__device__ __forceinline__ float to_tf32(float x) {
    asm("cvt.rna.tf32.f32 %0, %0;" : "+f"(x));
    return x;
}
__device__ __forceinline__ void mma_tf32(float* c,
                                         uint32_t a0, uint32_t a1, uint32_t a2, uint32_t a3,
                                         uint32_t b0, uint32_t b1) {
    asm volatile(
        "mma.sync.aligned.m16n8k8.row.col.f32.tf32.tf32.f32 "
        "{%0,%1,%2,%3}, {%4,%5,%6,%7}, {%8,%9}, {%0,%1,%2,%3};"
        : "+f"(c[0]), "+f"(c[1]), "+f"(c[2]), "+f"(c[3])
        : "r"(a0), "r"(a1), "r"(a2), "r"(a3), "r"(b0), "r"(b1));
}

// ---------------------------------------------------------------------------
// K0: transpose weights (w_qkv [128,384] -> [384,128]; w_out [128,128] -> T)
// ---------------------------------------------------------------------------
__global__ void transpose_w_kernel(const float* __restrict__ wqkv,
                                   const float* __restrict__ wout,
                                   float* __restrict__ wT)
{
    const int i = blockIdx.x * 256 + threadIdx.x;
    if (i < 49152) {
        const int k = i / 384, n = i - k * 384;
        wT[n * 128 + k] = wqkv[i];
    }
    if (i < 16384) {
        const int k = i >> 7, n = i & 127;
        wT[49152 + n * 128 + k] = wout[i];
    }
}

// ---------------------------------------------------------------------------
// K2: fused LN + window partition + QKV GEMM. 64x128 tile (2 CTAs/SM),
// K=128 resident, 8 warps (2x4), warp 32x32, 16 k-steps, 3 N-blocks.
// ---------------------------------------------------------------------------
__global__ void __launch_bounds__(256, 2)
gemm_qkv_kernel(const float* __restrict__ A,       // raw x [B,56,56,128]
                const float* __restrict__ WT,      // [384, 128] row-major
                const float* __restrict__ bias,
                const float* __restrict__ gamma,
                const float* __restrict__ beta,
                float* __restrict__ out)
{
    extern __shared__ float sm[];
    float* As = sm;                          // [64][SMEM_LDA]
    float* Bs = sm + 64 * SMEM_LDA;          // [128][SMEM_LDA]

    const int tid  = threadIdx.x;
    const int warp = tid >> 5, lane = tid & 31;
    const int wm = (warp >> 2) * 32;
    const int wn = (warp & 3) * 32;
    const int qrow = lane >> 2;
    const int qcol = lane & 3;
    const int mBase = blockIdx.x * 64;

    // --- A fill: one full row per warp-iteration (lane = k4); LN fused ---
    float4 gm = reinterpret_cast<const float4*>(gamma)[lane];
    float4 bt = reinterpret_cast<const float4*>(beta)[lane];
    const float4* A4 = reinterpret_cast<const float4*>(A);
    #pragma unroll
    for (int j = 0; j < 8; j++) {
        const int m = warp + 8 * j;
        const int t = mBase + m;
        const int g = t / 49, p = t - g * 49;
        const int b = g >> 6, w = g & 63;
        const int row = (w >> 3) * 7 + p / 7;
        const int col = (w & 7) * 7 + p % 7;
        float4 v = A4[((size_t)b * 3136 + row * 56 + col) * 32 + lane];
        float sum = v.x + v.y + v.z + v.w;
        #pragma unroll
        for (int o = 16; o > 0; o >>= 1) sum += __shfl_xor_sync(0xffffffffu, sum, o);
        const float mu = sum * (1.0f / 128.0f);
        float4 d;
        d.x = v.x - mu; d.y = v.y - mu; d.z = v.z - mu; d.w = v.w - mu;
        float sq = d.x * d.x + d.y * d.y + d.z * d.z + d.w * d.w;
        #pragma unroll
        for (int o = 16; o > 0; o >>= 1) sq += __shfl_xor_sync(0xffffffffu, sq, o);
        const float rstd = rsqrtf(sq * (1.0f / 128.0f) + LN_EPS);
        v.x = to_tf32(d.x * rstd * gm.x + bt.x);
        v.y = to_tf32(d.y * rstd * gm.y + bt.y);
        v.z = to_tf32(d.z * rstd * gm.z + bt.z);
        v.w = to_tf32(d.w * rstd * gm.w + bt.w);
        *reinterpret_cast<float4*>(&As[m * SMEM_LDA + lane * 4]) = v;
    }

    const float* aBase = As + (wm + qrow) * SMEM_LDA + qcol;
    const float* bBase = Bs + (wn + qrow) * SMEM_LDA + qcol;
    const float4* W4 = reinterpret_cast<const float4*>(WT);

    for (int y = 0; y < 3; y++) {
        const int nBase = y * 128;

        #pragma unroll
        for (int i = tid; i < 4096; i += 256) {
            const int n = i >> 5, k4 = i & 31;
            float4 v = W4[(size_t)(nBase + n) * 32 + k4];
            v.x = to_tf32(v.x); v.y = to_tf32(v.y);
            v.z = to_tf32(v.z); v.w = to_tf32(v.w);
            *reinterpret_cast<float4*>(&Bs[n * SMEM_LDA + k4 * 4]) = v;
        }
        __syncthreads();

        float acc[2][4][4];
        #pragma unroll
        for (int i = 0; i < 2; i++)
            #pragma unroll
            for (int j = 0; j < 4; j++)
                #pragma unroll
                for (int r = 0; r < 4; r++) acc[i][j][r] = 0.0f;

        #pragma unroll
        for (int ks = 0; ks < 16; ks++) {
            const int kk = ks * 8;
            uint32_t af[2][4];
            #pragma unroll
            for (int i = 0; i < 2; i++) {
                const float* ap = aBase + i * 16 * SMEM_LDA + kk;
                af[i][0] = __float_as_uint(ap[0]);
                af[i][1] = __float_as_uint(ap[8 * SMEM_LDA]);
                af[i][2] = __float_as_uint(ap[4]);
                af[i][3] = __float_as_uint(ap[8 * SMEM_LDA + 4]);
            }
            uint32_t bf[4][2];
            #pragma unroll
            for (int j = 0; j < 4; j++) {
                const float* bp = bBase + j * 8 * SMEM_LDA + kk;
                bf[j][0] = __float_as_uint(bp[0]);
                bf[j][1] = __float_as_uint(bp[4]);
            }
            #pragma unroll
            for (int i = 0; i < 2; i++)
                #pragma unroll
                for (int j = 0; j < 4; j++)
                    mma_tf32(acc[i][j], af[i][0], af[i][1], af[i][2], af[i][3],
                             bf[j][0], bf[j][1]);
        }

        #pragma unroll
        for (int i = 0; i < 2; i++) {
            #pragma unroll
            for (int half = 0; half < 2; half++) {
                const int t = mBase + wm + i * 16 + qrow + half * 8;
                const int g = t / 49, p = t - g * 49;
                #pragma unroll
                for (int j = 0; j < 4; j++) {
                    const int jj = nBase + wn + j * 8 + 2 * qcol;
                    const int which = jj >> 7;
                    const int ch = jj & 127;
                    const int h = ch >> 4, d = ch & 15;
                    float2 v;
                    v.x = acc[i][j][half * 2 + 0] + __ldg(&bias[jj]);
                    v.y = acc[i][j][half * 2 + 1] + __ldg(&bias[jj + 1]);
                    *reinterpret_cast<float2*>(
                        out + (size_t)which * QKV_STRIDE +
                        ((size_t)((g * 8 + h) * 49 + p)) * 16 + d) = v;
                }
            }
        }
        __syncthreads();
    }
}

// ---------------------------------------------------------------------------
// K3: fused attention + out-projection. One block per window, 512 threads
// (16 warps = 8 heads x 2 warps). Attention math identical to R7/R9.
// O written (tf32-rounded) to smem tile os[64][132]; then all 16 warps run
// the out-proj mainloop (warp tile 16x32) and window-merge scatter to d_out.
// smem: 8 head slabs (94208 B) + os (33792 B) + Bs (67584 B) = 195584 B.
// ---------------------------------------------------------------------------
#define ATT_WSLAB 2944               // floats per head slab
#define OS_OFF    (8 * ATT_WSLAB)    // 23552 floats
#define BS_OFF    (OS_OFF + 64 * SMEM_LDA)          // 23552 + 8448 = 32000
#define FUSED_SMEM ((BS_OFF + 128 * SMEM_LDA) * 4)  // 195584 bytes

__global__ void __launch_bounds__(512, 1)
attn_proj_kernel(const float* __restrict__ qkv,
                 const float* __restrict__ WToutT,   // [128,128] (w_out^T)
                 const float* __restrict__ bias,
                 float* __restrict__ out)
{
    extern __shared__ float smd[];
    const int g     = blockIdx.x;                 // window
    const int tid   = threadIdx.x;
    const int hloc  = tid >> 6;                   // 0..7 head
    const int rowhalf = (tid >> 5) & 1;
    const int wt    = tid & 63;
    const int lane  = tid & 31;
    const int qrow  = lane >> 2;
    const int qcol  = lane & 3;
    const int wh    = g * 8 + hloc;

    float* qs  = smd + hloc * ATT_WSLAB;          // [49][20]
    float* ks_ = qs + 980;                        // [49][20]
    float* vt  = qs + 1960;                       // [16][60]
    float* os  = smd + OS_OFF;                    // [64][132]  (proj A)
    float* bs  = smd + BS_OFF;                    // [128][132] (proj B)

    const float* qp = qkv + (size_t)wh * 784;
    const float* kp = qp + QKV_STRIDE;
    const float* vp = qp + 2 * (size_t)QKV_STRIDE;

    // --- proj B fill (independent of attention) ---
    const float4* W4 = reinterpret_cast<const float4*>(WToutT);
    #pragma unroll
    for (int i = tid; i < 4096; i += 512) {
        const int n = i >> 5, k4 = i & 31;
        float4 v = W4[n * 32 + k4];
        v.x = to_tf32(v.x); v.y = to_tf32(v.y);
        v.z = to_tf32(v.z); v.w = to_tf32(v.w);
        *reinterpret_cast<float4*>(&bs[n * SMEM_LDA + k4 * 4]) = v;
    }
    // zero os pad rows 49..63
    for (int i = tid; i < 15 * SMEM_LDA; i += 512) os[49 * SMEM_LDA + i] = 0.0f;

    // zero Vt pad cols 49..59
    for (int i = wt; i < 176; i += 64) {
        const int d = i / 11, c = 49 + (i % 11);
        vt[d * 60 + c] = 0.0f;
    }
    // fill Q (scale folded), K, Vt — 64 threads per head
    for (int idx = wt; idx < 196; idx += 64) {
        const int row = idx >> 2, c4 = (idx & 3) * 4;
        float4 q = reinterpret_cast<const float4*>(qp)[idx];
        q.x *= SCALE_ATT; q.y *= SCALE_ATT; q.z *= SCALE_ATT; q.w *= SCALE_ATT;
        *reinterpret_cast<float4*>(&qs[row * 20 + c4]) = q;
        float4 k = reinterpret_cast<const float4*>(kp)[idx];
        *reinterpret_cast<float4*>(&ks_[row * 20 + c4]) = k;
        float4 v = reinterpret_cast<const float4*>(vp)[idx];
        vt[(c4 + 0) * 60 + row] = v.x;
        vt[(c4 + 1) * 60 + row] = v.y;
        vt[(c4 + 2) * 60 + row] = v.z;
        vt[(c4 + 3) * 60 + row] = v.w;
    }
    __syncthreads();

    // ---- scores: S = Q K^T (rounded tf32) ----
    float sc[2][7][4];
    #pragma unroll
    for (int i = 0; i < 2; i++)
        #pragma unroll
        for (int j = 0; j < 7; j++)
            #pragma unroll
            for (int r = 0; r < 4; r++) sc[i][j][r] = 0.0f;

    #pragma unroll
    for (int ks = 0; ks < 2; ks++) {
        const int kk = ks * 8;
        uint32_t ah[2][4];
        #pragma unroll
        for (int i = 0; i < 2; i++) {
            const int it = rowhalf * 2 + i;
            const float* ap = qs + (it * 16 + qrow) * 20 + kk + qcol;
            ah[i][0] = __float_as_uint(to_tf32(ap[0]));
            ah[i][1] = __float_as_uint(to_tf32(ap[160]));
            ah[i][2] = __float_as_uint(to_tf32(ap[4]));
            ah[i][3] = __float_as_uint(to_tf32(ap[164]));
        }
        #pragma unroll
        for (int j = 0; j < 7; j++) {
            const float* bp = ks_ + (j * 8 + qrow) * 20 + kk + qcol;
            const uint32_t Bh0 = __float_as_uint(to_tf32(bp[0]));
            const uint32_t Bh1 = __float_as_uint(to_tf32(bp[4]));
            #pragma unroll
            for (int i = 0; i < 2; i++)
                mma_tf32(sc[i][j], ah[i][0], ah[i][1], ah[i][2], ah[i][3], Bh0, Bh1);
        }
    }

    // ---- softmax in C layout ----
    float invlo[2], invhi[2];
    #pragma unroll
    for (int i = 0; i < 2; i++) {
        if (qcol != 0) { sc[i][6][0] = -1e30f; sc[i][6][2] = -1e30f; }
        sc[i][6][1] = -1e30f; sc[i][6][3] = -1e30f;

        float mlo = -1e30f, mhi = -1e30f;
        #pragma unroll
        for (int j = 0; j < 7; j++) {
            mlo = fmaxf(mlo, fmaxf(sc[i][j][0], sc[i][j][1]));
            mhi = fmaxf(mhi, fmaxf(sc[i][j][2], sc[i][j][3]));
        }
        mlo = fmaxf(mlo, __shfl_xor_sync(0xffffffffu, mlo, 1));
        mlo = fmaxf(mlo, __shfl_xor_sync(0xffffffffu, mlo, 2));
        mhi = fmaxf(mhi, __shfl_xor_sync(0xffffffffu, mhi, 1));
        mhi = fmaxf(mhi, __shfl_xor_sync(0xffffffffu, mhi, 2));

        float slo = 0.0f, shi = 0.0f;
        #pragma unroll
        for (int j = 0; j < 7; j++) {
            sc[i][j][0] = __expf(sc[i][j][0] - mlo);
            sc[i][j][1] = __expf(sc[i][j][1] - mlo);
            sc[i][j][2] = __expf(sc[i][j][2] - mhi);
            sc[i][j][3] = __expf(sc[i][j][3] - mhi);
            slo += sc[i][j][0] + sc[i][j][1];
            shi += sc[i][j][2] + sc[i][j][3];
        }
        slo += __shfl_xor_sync(0xffffffffu, slo, 1);
        slo += __shfl_xor_sync(0xffffffffu, slo, 2);
        shi += __shfl_xor_sync(0xffffffffu, shi, 1);
        shi += __shfl_xor_sync(0xffffffffu, shi, 2);
        invlo[i] = 1.0f / slo;
        invhi[i] = 1.0f / shi;
    }

    // ---- PV: O = P V (C->A via shuffles) ----
    float oacc[2][2][4];
    #pragma unroll
    for (int i = 0; i < 2; i++)
        #pragma unroll
        for (int jn = 0; jn < 2; jn++)
            #pragma unroll
            for (int r = 0; r < 4; r++) oacc[i][jn][r] = 0.0f;

    const unsigned src0 = (lane & 28) | (qcol >> 1);
    const unsigned src1 = src0 + 2;
    const bool odd = (qcol & 1) != 0;

    #pragma unroll
    for (int kt = 0; kt < 7; kt++) {
        uint32_t Bh[2][2];
        #pragma unroll
        for (int jn = 0; jn < 2; jn++) {
            const float* bp = vt + (jn * 8 + qrow) * 60 + kt * 8 + qcol;
            Bh[jn][0] = __float_as_uint(to_tf32(bp[0]));
            Bh[jn][1] = __float_as_uint(to_tf32(bp[4]));
        }
        #pragma unroll
        for (int i = 0; i < 2; i++) {
            float t0 = __shfl_sync(0xffffffffu, sc[i][kt][0], src0);
            float t1 = __shfl_sync(0xffffffffu, sc[i][kt][1], src0);
            float u0 = __shfl_sync(0xffffffffu, sc[i][kt][0], src1);
            float u1 = __shfl_sync(0xffffffffu, sc[i][kt][1], src1);
            float t2 = __shfl_sync(0xffffffffu, sc[i][kt][2], src0);
            float t3 = __shfl_sync(0xffffffffu, sc[i][kt][3], src0);
            float u2 = __shfl_sync(0xffffffffu, sc[i][kt][2], src1);
            float u3 = __shfl_sync(0xffffffffu, sc[i][kt][3], src1);
            const uint32_t Ah0 = __float_as_uint(to_tf32(odd ? t1 : t0));
            const uint32_t Ah1 = __float_as_uint(to_tf32(odd ? t3 : t2));
            const uint32_t Ah2 = __float_as_uint(to_tf32(odd ? u1 : u0));
            const uint32_t Ah3 = __float_as_uint(to_tf32(odd ? u3 : u2));
            #pragma unroll
            for (int jn = 0; jn < 2; jn++)
                mma_tf32(oacc[i][jn], Ah0, Ah1, Ah2, Ah3, Bh[jn][0], Bh[jn][1]);
        }
    }

    // ---- store O into os (tf32-rounded, 1/rowsum folded) ----
    float* obase = os + hloc * 16;
    #pragma unroll
    for (int i = 0; i < 2; i++) {
        const int it = rowhalf * 2 + i;
        const int rlo = it * 16 + qrow;
        const int rhi = rlo + 8;
        #pragma unroll
        for (int jn = 0; jn < 2; jn++) {
            const int d = jn * 8 + 2 * qcol;
            if (rlo < 49) {
                float2 v;
                v.x = to_tf32(oacc[i][jn][0] * invlo[i]);
                v.y = to_tf32(oacc[i][jn][1] * invlo[i]);
                *reinterpret_cast<float2*>(obase + rlo * SMEM_LDA + d) = v;
            }
            if (rhi < 49) {
                float2 v;
                v.x = to_tf32(oacc[i][jn][2] * invhi[i]);
                v.y = to_tf32(oacc[i][jn][3] * invhi[i]);
                *reinterpret_cast<float2*>(obase + rhi * SMEM_LDA + d) = v;
            }
        }
    }
    __syncthreads();

    // ---- out-projection: 16 warps, warp tile 16x32, K=128 ----
    const int warp = tid >> 5;
    const int wm2 = (warp >> 2) * 16;
    const int wn2 = (warp & 3) * 32;
    const float* aBase = os + (wm2 + qrow) * SMEM_LDA + qcol;
    const float* bBase = bs + (wn2 + qrow) * SMEM_LDA + qcol;

    float acc[4][4];
    #pragma unroll
    for (int j = 0; j < 4; j++)
        #pragma unroll
        for (int r = 0; r < 4; r++) acc[j][r] = 0.0f;

    #pragma unroll
    for (int ks = 0; ks < 16; ks++) {
        const int kk = ks * 8;
        const float* ap = aBase + kk;
        const uint32_t a0 = __float_as_uint(ap[0]);
        const uint32_t a1 = __float_as_uint(ap[8 * SMEM_LDA]);
        const uint32_t a2 = __float_as_uint(ap[4]);
        const uint32_t a3 = __float_as_uint(ap[8 * SMEM_LDA + 4]);
        #pragma unroll
        for (int j = 0; j < 4; j++) {
            const float* bp = bBase + j * 8 * SMEM_LDA + kk;
            const uint32_t b0 = __float_as_uint(bp[0]);
            const uint32_t b1 = __float_as_uint(bp[4]);
            mma_tf32(acc[j], a0, a1, a2, a3, b0, b1);
        }
    }

    // ---- epilogue: +bias, window-merge scatter ----
    const int b = g >> 6, w = g & 63;
    #pragma unroll
    for (int half = 0; half < 2; half++) {
        const int p = wm2 + qrow + half * 8;
        if (p < 49) {
            const int row = (w >> 3) * 7 + p / 7;
            const int col = (w & 7) * 7 + p % 7;
            float* op = out + ((size_t)b * 3136 + row * 56 + col) * 128;
            #pragma unroll
            for (int j = 0; j < 4; j++) {
                const int cofs = wn2 + j * 8 + 2 * qcol;
                float2 v;
                v.x = acc[j][half * 2 + 0] + __ldg(&bias[cofs]);
                v.y = acc[j][half * 2 + 1] + __ldg(&bias[cofs + 1]);
                *reinterpret_cast<float2*>(op + cofs) = v;
            }
        }
    }
}

// ---------------------------------------------------------------------------
// Launch
// ---------------------------------------------------------------------------
extern "C" void kernel_launch(void* const* d_in, const int* in_sizes, int n_in,
                              void* d_out, int out_size)
{
    const float* x       = (const float*)d_in[0];
    const float* ln_g    = (const float*)d_in[1];
    const float* ln_b    = (const float*)d_in[2];
    const float* w_qkv   = (const float*)d_in[3];
    const float* b_qkv   = (const float*)d_in[4];
    const float* w_out   = (const float*)d_in[5];
    const float* b_out   = (const float*)d_in[6];
    float* out           = (float*)d_out;

    void *qkv_ptr = nullptr, *wT_ptr = nullptr;
    cudaGetSymbolAddress(&qkv_ptr, g_qkv);
    cudaGetSymbolAddress(&wT_ptr, g_wT);
    float* qkv = (float*)qkv_ptr;
    float* wT  = (float*)wT_ptr;

    const int smemG = (64 + 128) * SMEM_LDA * sizeof(float);  // 101376 B
    cudaFuncSetAttribute((const void*)gemm_qkv_kernel,
                         cudaFuncAttributeMaxDynamicSharedMemorySize, smemG);
    cudaFuncSetAttribute((const void*)attn_proj_kernel,
                         cudaFuncAttributeMaxDynamicSharedMemorySize, FUSED_SMEM);

    // K0: weight transpose (tiny)
    transpose_w_kernel<<<192, 256>>>(w_qkv, w_out, wT);

    // K2: fused LN + window partition + QKV GEMM (M=200704, N=384, K=128)
    gemm_qkv_kernel<<<NTOK / 64, 256, smemG>>>(x, wT, b_qkv, ln_g, ln_b, qkv);

    // K3: fused attention + out-projection + window merge
    attn_proj_kernel<<<4096, 512, FUSED_SMEM>>>(qkv, wT + 49152, b_out, out);
}

// round 11
// speedup vs baseline: 1.0690x; 1.0690x over previous
#include <cuda_runtime.h>
#include <cstdint>

// ---------------------------------------------------------------------------
// Window-based self-attention (Swin-style), B=64, 56x56, C=128, WS=7, NH=8.
// Round 11: revert to R9 structure (best). GEMMs get paired-k fragment
// layout (LDS.64 frag loads, LDA=136) + W pre-rounded/pre-permuted in K0.
//   K0: transpose + tf32-round + k-permute weights -> g_wT
//   K2: fused LN + window partition + QKV GEMM -> g_qkv
//   K3: tensor-core attention (tf32) -> g_xw
//   K4: out-proj GEMM + window merge -> d_out
// ---------------------------------------------------------------------------

#define NTOK      200704            // 4096 windows * 49 tokens
#define CDIM      128
#define QKV_STRIDE 25690112         // NTOK * CDIM
#define SCALE_ATT 0.25f             // HD^-0.5, HD=16
#define LN_EPS    1e-5f
#define SMEM_LDA  136               // padded row stride (floats); 136%32=8 ->
                                    // conflict-free LDS.64 frag loads

__device__ float g_xw[(size_t)NTOK * CDIM];          // attn out (K4 input)
__device__ float g_qkv[(size_t)3 * NTOK * CDIM];     // ~308 MB
__device__ float g_wT[384 * 128 + 128 * 128];        // wT_qkv | wT_out (tf32, k-permuted)

// ---------------------------------------------------------------------------
// helpers
// ---------------------------------------------------------------------------
__device__ __forceinline__ float to_tf32(float x) {
    asm("cvt.rna.tf32.f32 %0, %0;" : "+f"(x));
    return x;
}
__device__ __forceinline__ void mma_tf32(float* c,
                                         uint32_t a0, uint32_t a1, uint32_t a2, uint32_t a3,
                                         uint32_t b0, uint32_t b1) {
    asm volatile(
        "mma.sync.aligned.m16n8k8.row.col.f32.tf32.tf32.f32 "
        "{%0,%1,%2,%3}, {%4,%5,%6,%7}, {%8,%9}, {%0,%1,%2,%3};"
        : "+f"(c[0]), "+f"(c[1]), "+f"(c[2]), "+f"(c[3])
        : "r"(a0), "r"(a1), "r"(a2), "r"(a3), "r"(b0), "r"(b1));
}
// within each 8-k group, place (k, k+4) adjacent: pos = (k&3)*2 + ((k>>2)&1)
__device__ __forceinline__ int kperm(int k) {
    return (k & ~7) + ((k & 3) * 2) + ((k >> 2) & 1);
}

// ---------------------------------------------------------------------------
// K0: transpose + tf32-round + k-permute weights.
// w_qkv [128,384] -> wT[n*128 + kperm(k)]; w_out [128,128] likewise at +49152.
// ---------------------------------------------------------------------------
__global__ void transpose_w_kernel(const float* __restrict__ wqkv,
                                   const float* __restrict__ wout,
                                   float* __restrict__ wT)
{
    const int i = blockIdx.x * 256 + threadIdx.x;
    if (i < 49152) {
        const int k = i / 384, n = i - k * 384;
        wT[n * 128 + kperm(k)] = to_tf32(wqkv[i]);
    }
    if (i < 16384) {
        const int k = i >> 7, n = i & 127;
        wT[49152 + n * 128 + kperm(k)] = to_tf32(wout[i]);
    }
}

// ---------------------------------------------------------------------------
// K2/K4: tf32 mma.sync GEMM. 64x128 tile (2 CTAs/SM), K=128 resident,
// 8 warps (2x4), warp 32x32, 16 k-steps. Paired-k smem layout: fragment
// loads are LDS.64 (a-pairs, b-pairs adjacent).
// MODE 0 (NBLK=3): LN + window partition fused into A-fill; QKV scatter out.
// MODE 1 (NBLK=1): A = attention output; out-proj epilogue (+bias, merge).
// ---------------------------------------------------------------------------
template <int MODE, int NBLK>
__global__ void __launch_bounds__(256, 2)
gemm_mma_kernel(const float* __restrict__ A,
                const float* __restrict__ WT,      // [N_total,128] tf32, k-permuted
                const float* __restrict__ bias,
                const float* __restrict__ gamma,   // MODE 0 only
                const float* __restrict__ beta,    // MODE 0 only
                float* __restrict__ out)
{
    extern __shared__ float sm[];
    float* As = sm;                          // [64][SMEM_LDA]  (k-permuted)
    float* Bs = sm + 64 * SMEM_LDA;          // [128][SMEM_LDA] (k-permuted)

    const int tid  = threadIdx.x;
    const int warp = tid >> 5, lane = tid & 31;
    const int wm = (warp >> 2) * 32;
    const int wn = (warp & 3) * 32;
    const int qrow = lane >> 2;
    const int qcol = lane & 3;
    const int mBase = blockIdx.x * 64;

    // --- A fill: one full row per warp-iteration (lane = k4 group) ---
    float4 gm, bt;
    if (MODE == 0) {
        gm = reinterpret_cast<const float4*>(gamma)[lane];
        bt = reinterpret_cast<const float4*>(beta)[lane];
    }
    const float4* A4 = reinterpret_cast<const float4*>(A);
    const int rot = (lane >> 3) & 3;         // STS bank-rotation
    #pragma unroll
    for (int j = 0; j < 8; j++) {
        const int m = warp + 8 * j;
        const int t = mBase + m;
        float4 v;
        if (MODE == 0) {
            const int g = t / 49, p = t - g * 49;
            const int b = g >> 6, w = g & 63;
            const int row = (w >> 3) * 7 + p / 7;
            const int col = (w & 7) * 7 + p % 7;
            v = A4[((size_t)b * 3136 + row * 56 + col) * 32 + lane];
            float sum = v.x + v.y + v.z + v.w;
            #pragma unroll
            for (int o = 16; o > 0; o >>= 1) sum += __shfl_xor_sync(0xffffffffu, sum, o);
            const float mu = sum * (1.0f / 128.0f);
            float4 d;
            d.x = v.x - mu; d.y = v.y - mu; d.z = v.z - mu; d.w = v.w - mu;
            float sq = d.x * d.x + d.y * d.y + d.z * d.z + d.w * d.w;
            #pragma unroll
            for (int o = 16; o > 0; o >>= 1) sq += __shfl_xor_sync(0xffffffffu, sq, o);
            const float rstd = rsqrtf(sq * (1.0f / 128.0f) + LN_EPS);
            v.x = to_tf32(d.x * rstd * gm.x + bt.x);
            v.y = to_tf32(d.y * rstd * gm.y + bt.y);
            v.z = to_tf32(d.z * rstd * gm.z + bt.z);
            v.w = to_tf32(d.w * rstd * gm.w + bt.w);
        } else {
            v = A4[(size_t)t * 32 + lane];
            v.x = to_tf32(v.x); v.y = to_tf32(v.y);
            v.z = to_tf32(v.z); v.w = to_tf32(v.w);
        }
        // permuted scatter: component c (k = 4*lane + c) -> pos 2c + (lane&1)
        // within group (lane>>1); rotate store order by lane>>3 (bank spread).
        const float vals[4] = {v.x, v.y, v.z, v.w};
        float* abase = &As[m * SMEM_LDA + (lane >> 1) * 8 + (lane & 1)];
        #pragma unroll
        for (int s = 0; s < 4; s++) {
            const int c = (s + rot) & 3;
            abase[2 * c] = vals[c];
        }
    }

    const float* aBase = As + (wm + qrow) * SMEM_LDA + 2 * qcol;
    const float* bBase = Bs + (wn + qrow) * SMEM_LDA + 2 * qcol;
    const float4* W4 = reinterpret_cast<const float4*>(WT);

    for (int y = 0; y < NBLK; y++) {
        const int nBase = y * 128;

        // B fill: pure float4 copy (pre-rounded, pre-permuted in K0)
        #pragma unroll
        for (int i = tid; i < 4096; i += 256) {
            const int n = i >> 5, k4 = i & 31;
            *reinterpret_cast<float4*>(&Bs[n * SMEM_LDA + k4 * 4]) =
                W4[(size_t)(nBase + n) * 32 + k4];
        }
        __syncthreads();

        float acc[2][4][4];
        #pragma unroll
        for (int i = 0; i < 2; i++)
            #pragma unroll
            for (int j = 0; j < 4; j++)
                #pragma unroll
                for (int r = 0; r < 4; r++) acc[i][j][r] = 0.0f;

        #pragma unroll
        for (int ks = 0; ks < 16; ks++) {
            const int kk = ks * 8;
            float2 alo[2], ahi[2];
            #pragma unroll
            for (int i = 0; i < 2; i++) {
                alo[i] = *reinterpret_cast<const float2*>(aBase + i * 16 * SMEM_LDA + kk);
                ahi[i] = *reinterpret_cast<const float2*>(aBase + i * 16 * SMEM_LDA + 8 * SMEM_LDA + kk);
            }
            float2 bv[4];
            #pragma unroll
            for (int j = 0; j < 4; j++)
                bv[j] = *reinterpret_cast<const float2*>(bBase + j * 8 * SMEM_LDA + kk);
            #pragma unroll
            for (int i = 0; i < 2; i++)
                #pragma unroll
                for (int j = 0; j < 4; j++)
                    mma_tf32(acc[i][j],
                             __float_as_uint(alo[i].x), __float_as_uint(ahi[i].x),
                             __float_as_uint(alo[i].y), __float_as_uint(ahi[i].y),
                             __float_as_uint(bv[j].x),  __float_as_uint(bv[j].y));
        }

        #pragma unroll
        for (int i = 0; i < 2; i++) {
            #pragma unroll
            for (int half = 0; half < 2; half++) {
                const int t = mBase + wm + i * 16 + qrow + half * 8;
                const int g = t / 49, p = t - g * 49;
                if (MODE == 0) {
                    #pragma unroll
                    for (int j = 0; j < 4; j++) {
                        const int jj = nBase + wn + j * 8 + 2 * qcol;
                        const int which = jj >> 7;
                        const int ch = jj & 127;
                        const int h = ch >> 4, d = ch & 15;
                        float2 v;
                        v.x = acc[i][j][half * 2 + 0] + __ldg(&bias[jj]);
                        v.y = acc[i][j][half * 2 + 1] + __ldg(&bias[jj + 1]);
                        *reinterpret_cast<float2*>(
                            out + (size_t)which * QKV_STRIDE +
                            ((size_t)((g * 8 + h) * 49 + p)) * 16 + d) = v;
                    }
                } else {
                    const int b = g >> 6, w = g & 63;
                    const int row = (w >> 3) * 7 + p / 7;
                    const int col = (w & 7) * 7 + p % 7;
                    float* op = out + ((size_t)b * 3136 + row * 56 + col) * 128;
                    #pragma unroll
                    for (int j = 0; j < 4; j++) {
                        const int cofs = wn + j * 8 + 2 * qcol;
                        float2 v;
                        v.x = acc[i][j][half * 2 + 0] + __ldg(&bias[cofs]);
                        v.y = acc[i][j][half * 2 + 1] + __ldg(&bias[cofs + 1]);
                        *reinterpret_cast<float2*>(op + cofs) = v;
                    }
                }
            }
        }
        __syncthreads();
    }
}

// ---------------------------------------------------------------------------
// K3: tensor-core attention, 2 warps per (window, head), single-pass tf32.
// Block = 8 warps = 4 heads; grid = 8192. (Unchanged from R9 — proven.)
// ---------------------------------------------------------------------------
#define ATT_WSLAB 2944   // floats per head slab (980 + 980 + 960 + pad)

__global__ void __launch_bounds__(256, 2)
attn_mma_kernel(const float* __restrict__ qkv, float* __restrict__ attnOut)
{
    extern __shared__ float smd[];
    const int g     = blockIdx.x >> 1;            // window
    const int hbase = (blockIdx.x & 1) * 4;       // head group
    const int tid   = threadIdx.x;
    const int hloc  = tid >> 6;                   // 0..3 local head
    const int rowhalf = (tid >> 5) & 1;           // warp's row half
    const int wt    = tid & 63;
    const int lane  = tid & 31;
    const int qrow  = lane >> 2;
    const int qcol  = lane & 3;
    const int head  = hbase + hloc;
    const int wh    = g * 8 + head;

    float* qs  = smd + hloc * ATT_WSLAB;          // [49][20]
    float* ks_ = qs + 980;                        // [49][20]
    float* vt  = qs + 1960;                       // [16][60]  (V transposed)

    const float* qp = qkv + (size_t)wh * 784;
    const float* kp = qp + QKV_STRIDE;
    const float* vp = qp + 2 * (size_t)QKV_STRIDE;

    // zero Vt pad cols 49..59
    for (int i = wt; i < 176; i += 64) {
        const int d = i / 11, c = 49 + (i % 11);
        vt[d * 60 + c] = 0.0f;
    }
    // fill Q (scale folded), K, Vt — 64 threads per head
    for (int idx = wt; idx < 196; idx += 64) {
        const int row = idx >> 2, c4 = (idx & 3) * 4;
        float4 q = reinterpret_cast<const float4*>(qp)[idx];
        q.x *= SCALE_ATT; q.y *= SCALE_ATT; q.z *= SCALE_ATT; q.w *= SCALE_ATT;
        *reinterpret_cast<float4*>(&qs[row * 20 + c4]) = q;
        float4 k = reinterpret_cast<const float4*>(kp)[idx];
        *reinterpret_cast<float4*>(&ks_[row * 20 + c4]) = k;
        float4 v = reinterpret_cast<const float4*>(vp)[idx];
        vt[(c4 + 0) * 60 + row] = v.x;
        vt[(c4 + 1) * 60 + row] = v.y;
        vt[(c4 + 2) * 60 + row] = v.z;
        vt[(c4 + 3) * 60 + row] = v.w;
    }
    __syncthreads();

    // ---- scores: S = Q K^T (single-pass rounded tf32) ----
    float sc[2][7][4];
    #pragma unroll
    for (int i = 0; i < 2; i++)
        #pragma unroll
        for (int j = 0; j < 7; j++)
            #pragma unroll
            for (int r = 0; r < 4; r++) sc[i][j][r] = 0.0f;

    #pragma unroll
    for (int ks = 0; ks < 2; ks++) {
        const int kk = ks * 8;
        uint32_t ah[2][4];
        #pragma unroll
        for (int i = 0; i < 2; i++) {
            const int it = rowhalf * 2 + i;
            const float* ap = qs + (it * 16 + qrow) * 20 + kk + qcol;
            ah[i][0] = __float_as_uint(to_tf32(ap[0]));
            ah[i][1] = __float_as_uint(to_tf32(ap[160]));
            ah[i][2] = __float_as_uint(to_tf32(ap[4]));
            ah[i][3] = __float_as_uint(to_tf32(ap[164]));
        }
        #pragma unroll
        for (int j = 0; j < 7; j++) {
            const float* bp = ks_ + (j * 8 + qrow) * 20 + kk + qcol;
            const uint32_t Bh0 = __float_as_uint(to_tf32(bp[0]));
            const uint32_t Bh1 = __float_as_uint(to_tf32(bp[4]));
            #pragma unroll
            for (int i = 0; i < 2; i++)
                mma_tf32(sc[i][j], ah[i][0], ah[i][1], ah[i][2], ah[i][3], Bh0, Bh1);
        }
    }

    // ---- softmax in C layout ----
    float invlo[2], invhi[2];
    #pragma unroll
    for (int i = 0; i < 2; i++) {
        if (qcol != 0) { sc[i][6][0] = -1e30f; sc[i][6][2] = -1e30f; }
        sc[i][6][1] = -1e30f; sc[i][6][3] = -1e30f;

        float mlo = -1e30f, mhi = -1e30f;
        #pragma unroll
        for (int j = 0; j < 7; j++) {
            mlo = fmaxf(mlo, fmaxf(sc[i][j][0], sc[i][j][1]));
            mhi = fmaxf(mhi, fmaxf(sc[i][j][2], sc[i][j][3]));
        }
        mlo = fmaxf(mlo, __shfl_xor_sync(0xffffffffu, mlo, 1));
        mlo = fmaxf(mlo, __shfl_xor_sync(0xffffffffu, mlo, 2));
        mhi = fmaxf(mhi, __shfl_xor_sync(0xffffffffu, mhi, 1));
        mhi = fmaxf(mhi, __shfl_xor_sync(0xffffffffu, mhi, 2));

        float slo = 0.0f, shi = 0.0f;
        #pragma unroll
        for (int j = 0; j < 7; j++) {
            sc[i][j][0] = __expf(sc[i][j][0] - mlo);
            sc[i][j][1] = __expf(sc[i][j][1] - mlo);
            sc[i][j][2] = __expf(sc[i][j][2] - mhi);
            sc[i][j][3] = __expf(sc[i][j][3] - mhi);
            slo += sc[i][j][0] + sc[i][j][1];
            shi += sc[i][j][2] + sc[i][j][3];
        }
        slo += __shfl_xor_sync(0xffffffffu, slo, 1);
        slo += __shfl_xor_sync(0xffffffffu, slo, 2);
        shi += __shfl_xor_sync(0xffffffffu, shi, 1);
        shi += __shfl_xor_sync(0xffffffffu, shi, 2);
        invlo[i] = 1.0f / slo;
        invhi[i] = 1.0f / shi;
    }

    // ---- PV: O = P V (C->A via shuffles; single-pass tf32) ----
    float oacc[2][2][4];
    #pragma unroll
    for (int i = 0; i < 2; i++)
        #pragma unroll
        for (int jn = 0; jn < 2; jn++)
            #pragma unroll
            for (int r = 0; r < 4; r++) oacc[i][jn][r] = 0.0f;

    const unsigned src0 = (lane & 28) | (qcol >> 1);
    const unsigned src1 = src0 + 2;
    const bool odd = (qcol & 1) != 0;

    #pragma unroll
    for (int kt = 0; kt < 7; kt++) {
        uint32_t Bh[2][2];
        #pragma unroll
        for (int jn = 0; jn < 2; jn++) {
            const float* bp = vt + (jn * 8 + qrow) * 60 + kt * 8 + qcol;
            Bh[jn][0] = __float_as_uint(to_tf32(bp[0]));
            Bh[jn][1] = __float_as_uint(to_tf32(bp[4]));
        }
        #pragma unroll
        for (int i = 0; i < 2; i++) {
            float t0 = __shfl_sync(0xffffffffu, sc[i][kt][0], src0);
            float t1 = __shfl_sync(0xffffffffu, sc[i][kt][1], src0);
            float u0 = __shfl_sync(0xffffffffu, sc[i][kt][0], src1);
            float u1 = __shfl_sync(0xffffffffu, sc[i][kt][1], src1);
            float t2 = __shfl_sync(0xffffffffu, sc[i][kt][2], src0);
            float t3 = __shfl_sync(0xffffffffu, sc[i][kt][3], src0);
            float u2 = __shfl_sync(0xffffffffu, sc[i][kt][2], src1);
            float u3 = __shfl_sync(0xffffffffu, sc[i][kt][3], src1);
            const uint32_t Ah0 = __float_as_uint(to_tf32(odd ? t1 : t0));
            const uint32_t Ah1 = __float_as_uint(to_tf32(odd ? t3 : t2));
            const uint32_t Ah2 = __float_as_uint(to_tf32(odd ? u1 : u0));
            const uint32_t Ah3 = __float_as_uint(to_tf32(odd ? u3 : u2));
            #pragma unroll
            for (int jn = 0; jn < 2; jn++)
                mma_tf32(oacc[i][jn], Ah0, Ah1, Ah2, Ah3, Bh[jn][0], Bh[jn][1]);
        }
    }

    // ---- store (predicated rows < 49), 1/rowsum folded ----
    float* outBase = attnOut + (size_t)g * 49 * 128 + head * 16;
    #pragma unroll
    for (int i = 0; i < 2; i++) {
        const int it = rowhalf * 2 + i;
        const int rlo = it * 16 + qrow;
        const int rhi = rlo + 8;
        #pragma unroll
        for (int jn = 0; jn < 2; jn++) {
            const int d = jn * 8 + 2 * qcol;
            if (rlo < 49) {
                float2 v;
                v.x = oacc[i][jn][0] * invlo[i];
                v.y = oacc[i][jn][1] * invlo[i];
                *reinterpret_cast<float2*>(outBase + (size_t)rlo * 128 + d) = v;
            }
            if (rhi < 49) {
                float2 v;
                v.x = oacc[i][jn][2] * invhi[i];
                v.y = oacc[i][jn][3] * invhi[i];
                *reinterpret_cast<float2*>(outBase + (size_t)rhi * 128 + d) = v;
            }
        }
    }
}

// ---------------------------------------------------------------------------
// Launch
// ---------------------------------------------------------------------------
extern "C" void kernel_launch(void* const* d_in, const int* in_sizes, int n_in,
                              void* d_out, int out_size)
{
    const float* x       = (const float*)d_in[0];
    const float* ln_g    = (const float*)d_in[1];
    const float* ln_b    = (const float*)d_in[2];
    const float* w_qkv   = (const float*)d_in[3];
    const float* b_qkv   = (const float*)d_in[4];
    const float* w_out   = (const float*)d_in[5];
    const float* b_out   = (const float*)d_in[6];
    float* out           = (float*)d_out;

    void *xw_ptr = nullptr, *qkv_ptr = nullptr, *wT_ptr = nullptr;
    cudaGetSymbolAddress(&xw_ptr, g_xw);
    cudaGetSymbolAddress(&qkv_ptr, g_qkv);
    cudaGetSymbolAddress(&wT_ptr, g_wT);
    float* xw  = (float*)xw_ptr;
    float* qkv = (float*)qkv_ptr;
    float* wT  = (float*)wT_ptr;

    const int smemG = (64 + 128) * SMEM_LDA * sizeof(float);  // 104448 B
    const int smemA = 4 * ATT_WSLAB * sizeof(float);          // 47104 B
    cudaFuncSetAttribute((const void*)gemm_mma_kernel<0, 3>,
                         cudaFuncAttributeMaxDynamicSharedMemorySize, smemG);
    cudaFuncSetAttribute((const void*)gemm_mma_kernel<1, 1>,
                         cudaFuncAttributeMaxDynamicSharedMemorySize, smemG);
    cudaFuncSetAttribute((const void*)attn_mma_kernel,
                         cudaFuncAttributeMaxDynamicSharedMemorySize, smemA);

    // K0: weight transpose + tf32 round + k-permute (tiny)
    transpose_w_kernel<<<192, 256>>>(w_qkv, w_out, wT);

    // K2: fused LN + window partition + QKV GEMM (M=200704, N=384, K=128)
    gemm_mma_kernel<0, 3><<<NTOK / 64, 256, smemG>>>(x, wT, b_qkv, ln_g, ln_b, qkv);

    // K3: tensor-core attention (2 warps/head), writes into g_xw
    attn_mma_kernel<<<8192, 256, smemA>>>(qkv, xw);

    // K4: out projection + window merge
    gemm_mma_kernel<1, 1><<<NTOK / 64, 256, smemG>>>(xw, wT + 49152, b_out, nullptr, nullptr, out);
}

// round 12
// speedup vs baseline: 1.0901x; 1.0198x over previous
#include <cuda_runtime.h>
#include <cstdint>

// ---------------------------------------------------------------------------
// Window-based self-attention (Swin-style), B=64, 56x56, C=128, WS=7, NH=8.
// Round 12: K2+K3 fused into one per-window kernel (kills the 616MB g_qkv
// round-trip). One CTA = one window, 256 threads, 2 CTAs/SM.
//   K0: transpose + tf32-round + k-permute weights -> g_wT
//   KF: fused LN + window partition + QKV GEMM (W from L2) + attention -> g_xw
//   K4: out-proj GEMM + window merge -> d_out   (unchanged from R11)
// ---------------------------------------------------------------------------

#define NTOK      200704            // 4096 windows * 49 tokens
#define SCALE_ATT 0.25f             // HD^-0.5, HD=16
#define LN_EPS    1e-5f
#define SMEM_LDA  136               // K4 GEMM row stride (floats)
#define XS_LDA    132               // fused-kernel A row stride (floats)

__device__ float g_xw[(size_t)NTOK * 128];           // attn out (K4 input)
__device__ float g_wT[384 * 128 + 128 * 128];        // wT_qkv | wT_out (tf32, k-permuted)

// fused smem layout (floats):
//   [0 .. 8448)            xs[64][132]   (A tile; later aliased by vt slabs 8x960)
//   [8448 .. 24128)        8 x (q[49][20] | k[49][20])  = 8 x 1960
//   tail pad 256 floats (q/k frag reads of garbage rows 49..63 overrun slab end)
#define REG2_OFF   8448
#define FUSED_SMEM ((24128 + 256) * 4)   // 97536 B -> 2 CTAs/SM

// ---------------------------------------------------------------------------
// helpers
// ---------------------------------------------------------------------------
__device__ __forceinline__ float to_tf32(float x) {
    asm("cvt.rna.tf32.f32 %0, %0;" : "+f"(x));
    return x;
}
__device__ __forceinline__ void mma_tf32(float* c,
                                         uint32_t a0, uint32_t a1, uint32_t a2, uint32_t a3,
                                         uint32_t b0, uint32_t b1) {
    asm volatile(
        "mma.sync.aligned.m16n8k8.row.col.f32.tf32.tf32.f32 "
        "{%0,%1,%2,%3}, {%4,%5,%6,%7}, {%8,%9}, {%0,%1,%2,%3};"
        : "+f"(c[0]), "+f"(c[1]), "+f"(c[2]), "+f"(c[3])
        : "r"(a0), "r"(a1), "r"(a2), "r"(a3), "r"(b0), "r"(b1));
}
// within each 8-k group, place (k, k+4) adjacent: pos = (k&3)*2 + ((k>>2)&1)
__device__ __forceinline__ int kperm(int k) {
    return (k & ~7) + ((k & 3) * 2) + ((k >> 2) & 1);
}

// ---------------------------------------------------------------------------
// K0: transpose + tf32-round + k-permute weights.
// ---------------------------------------------------------------------------
__global__ void transpose_w_kernel(const float* __restrict__ wqkv,
                                   const float* __restrict__ wout,
                                   float* __restrict__ wT)
{
    const int i = blockIdx.x * 256 + threadIdx.x;
    if (i < 49152) {
        const int k = i / 384, n = i - k * 384;
        wT[n * 128 + kperm(k)] = to_tf32(wqkv[i]);
    }
    if (i < 16384) {
        const int k = i >> 7, n = i & 127;
        wT[49152 + n * 128 + kperm(k)] = to_tf32(wout[i]);
    }
}

// ---------------------------------------------------------------------------
// KF: fused LN + window partition + QKV GEMM + attention. 1 CTA = 1 window.
// 8 warps. GEMM: warp tile M64 x N16 (its head's 16 cols), 3 passes (q,k,v),
// B frags prefetched from L2 per 8-k chunk. Attention: warp = head, temporal
// rowhalf loop (R9 math verbatim). Writes O to g_xw (token-major).
// ---------------------------------------------------------------------------
__global__ void __launch_bounds__(256, 2)
fused_qkv_attn_kernel(const float* __restrict__ x,
                      const float* __restrict__ WT,     // [384][128] tf32 k-permuted
                      const float* __restrict__ bias,   // b_qkv [384]
                      const float* __restrict__ gamma,
                      const float* __restrict__ beta,
                      float* __restrict__ attnOut)
{
    extern __shared__ float smd[];
    float* xs = smd;                              // [64][132]
    const int g    = blockIdx.x;                  // window
    const int tid  = threadIdx.x;
    const int warp = tid >> 5;                    // head / GEMM warp
    const int lane = tid & 31;
    const int qrow = lane >> 2;
    const int qcol = lane & 3;

    float* qs_h = smd + REG2_OFF + warp * 1960;   // [49][20]
    float* ks_h = qs_h + 980;                     // [49][20]
    float* vt_h = smd + warp * 960;               // [16][60], aliases xs

    // ---- Phase A: gather + LayerNorm -> xs rows 0..48 (tf32-rounded) ----
    {
        float4 gm = reinterpret_cast<const float4*>(gamma)[lane];
        float4 bt = reinterpret_cast<const float4*>(beta)[lane];
        const float4* X4 = reinterpret_cast<const float4*>(x);
        const int b = g >> 6, w = g & 63;
        for (int p = warp; p < 49; p += 8) {
            const int row = (w >> 3) * 7 + p / 7;
            const int col = (w & 7) * 7 + p % 7;
            float4 v = X4[((size_t)b * 3136 + row * 56 + col) * 32 + lane];
            float sum = v.x + v.y + v.z + v.w;
            #pragma unroll
            for (int o = 16; o > 0; o >>= 1) sum += __shfl_xor_sync(0xffffffffu, sum, o);
            const float mu = sum * (1.0f / 128.0f);
            float4 d;
            d.x = v.x - mu; d.y = v.y - mu; d.z = v.z - mu; d.w = v.w - mu;
            float sq = d.x * d.x + d.y * d.y + d.z * d.z + d.w * d.w;
            #pragma unroll
            for (int o = 16; o > 0; o >>= 1) sq += __shfl_xor_sync(0xffffffffu, sq, o);
            const float rstd = rsqrtf(sq * (1.0f / 128.0f) + LN_EPS);
            v.x = to_tf32(d.x * rstd * gm.x + bt.x);
            v.y = to_tf32(d.y * rstd * gm.y + bt.y);
            v.z = to_tf32(d.z * rstd * gm.z + bt.z);
            v.w = to_tf32(d.w * rstd * gm.w + bt.w);
            *reinterpret_cast<float4*>(&xs[p * XS_LDA + lane * 4]) = v;
        }
    }
    __syncthreads();

    // ---- Phase B: QKV GEMM, 3 passes (q, k, v) ----
    #pragma unroll 1
    for (int pass = 0; pass < 3; pass++) {
        const float* wp = WT + (size_t)(pass * 128 + warp * 16) * 128;

        float acc[4][2][4];
        #pragma unroll
        for (int i = 0; i < 4; i++)
            #pragma unroll
            for (int j = 0; j < 2; j++)
                #pragma unroll
                for (int r = 0; r < 4; r++) acc[i][j][r] = 0.0f;

        #pragma unroll
        for (int ch = 0; ch < 2; ch++) {
            // prefetch B frags for 8 k-steps (16 LDG.64, L2-hot)
            float2 bb[8][2];
            #pragma unroll
            for (int s = 0; s < 8; s++) {
                const int kk = ch * 64 + s * 8;
                bb[s][0] = *reinterpret_cast<const float2*>(wp + qrow * 128 + kk + 2 * qcol);
                bb[s][1] = *reinterpret_cast<const float2*>(wp + (8 + qrow) * 128 + kk + 2 * qcol);
            }
            #pragma unroll
            for (int s = 0; s < 8; s++) {
                const int kk = ch * 64 + s * 8;
                #pragma unroll
                for (int i = 0; i < 4; i++) {
                    const float* ap = xs + (i * 16 + qrow) * XS_LDA + kk + qcol;
                    const uint32_t a0 = __float_as_uint(ap[0]);
                    const uint32_t a1 = __float_as_uint(ap[8 * XS_LDA]);
                    const uint32_t a2 = __float_as_uint(ap[4]);
                    const uint32_t a3 = __float_as_uint(ap[8 * XS_LDA + 4]);
                    mma_tf32(acc[i][0], a0, a1, a2, a3,
                             __float_as_uint(bb[s][0].x), __float_as_uint(bb[s][0].y));
                    mma_tf32(acc[i][1], a0, a1, a2, a3,
                             __float_as_uint(bb[s][1].x), __float_as_uint(bb[s][1].y));
                }
            }
        }

        // before v epilogue (vt aliases xs) all warps must be done reading xs
        if (pass == 2) __syncthreads();

        // epilogue: scatter into this head's slabs
        #pragma unroll
        for (int i = 0; i < 4; i++) {
            #pragma unroll
            for (int half = 0; half < 2; half++) {
                const int r = i * 16 + qrow + half * 8;
                if (r < 49) {
                    #pragma unroll
                    for (int j = 0; j < 2; j++) {
                        const int d = j * 8 + 2 * qcol;
                        const int bidx = pass * 128 + warp * 16 + d;
                        float vx = acc[i][j][half * 2 + 0] + __ldg(&bias[bidx]);
                        float vy = acc[i][j][half * 2 + 1] + __ldg(&bias[bidx + 1]);
                        if (pass == 0) {
                            float2 v; v.x = vx * SCALE_ATT; v.y = vy * SCALE_ATT;
                            *reinterpret_cast<float2*>(&qs_h[r * 20 + d]) = v;
                        } else if (pass == 1) {
                            float2 v; v.x = vx; v.y = vy;
                            *reinterpret_cast<float2*>(&ks_h[r * 20 + d]) = v;
                        } else {
                            vt_h[d * 60 + r] = vx;
                            vt_h[(d + 1) * 60 + r] = vy;
                        }
                    }
                }
            }
        }
    }

    // zero vt pad cols 49..59 (read by PV k-tile 6)
    for (int i2 = lane; i2 < 176; i2 += 32) {
        const int d = i2 / 11, c = 49 + i2 % 11;
        vt_h[d * 60 + c] = 0.0f;
    }
    __syncwarp();

    // ---- Phase C: attention (warp = head), temporal rowhalf loop ----
    float* outBase = attnOut + (size_t)g * 49 * 128 + warp * 16;
    #pragma unroll 1
    for (int rowhalf = 0; rowhalf < 2; rowhalf++) {
        // scores S = Q K^T (single-pass rounded tf32)
        float sc[2][7][4];
        #pragma unroll
        for (int i = 0; i < 2; i++)
            #pragma unroll
            for (int j = 0; j < 7; j++)
                #pragma unroll
                for (int r = 0; r < 4; r++) sc[i][j][r] = 0.0f;

        #pragma unroll
        for (int ks = 0; ks < 2; ks++) {
            const int kk = ks * 8;
            uint32_t ah[2][4];
            #pragma unroll
            for (int i = 0; i < 2; i++) {
                const int it = rowhalf * 2 + i;
                const float* ap = qs_h + (it * 16 + qrow) * 20 + kk + qcol;
                ah[i][0] = __float_as_uint(to_tf32(ap[0]));
                ah[i][1] = __float_as_uint(to_tf32(ap[160]));
                ah[i][2] = __float_as_uint(to_tf32(ap[4]));
                ah[i][3] = __float_as_uint(to_tf32(ap[164]));
            }
            #pragma unroll
            for (int j = 0; j < 7; j++) {
                const float* bp = ks_h + (j * 8 + qrow) * 20 + kk + qcol;
                const uint32_t Bh0 = __float_as_uint(to_tf32(bp[0]));
                const uint32_t Bh1 = __float_as_uint(to_tf32(bp[4]));
                #pragma unroll
                for (int i = 0; i < 2; i++)
                    mma_tf32(sc[i][j], ah[i][0], ah[i][1], ah[i][2], ah[i][3], Bh0, Bh1);
            }
        }

        // softmax in C layout
        float invlo[2], invhi[2];
        #pragma unroll
        for (int i = 0; i < 2; i++) {
            if (qcol != 0) { sc[i][6][0] = -1e30f; sc[i][6][2] = -1e30f; }
            sc[i][6][1] = -1e30f; sc[i][6][3] = -1e30f;

            float mlo = -1e30f, mhi = -1e30f;
            #pragma unroll
            for (int j = 0; j < 7; j++) {
                mlo = fmaxf(mlo, fmaxf(sc[i][j][0], sc[i][j][1]));
                mhi = fmaxf(mhi, fmaxf(sc[i][j][2], sc[i][j][3]));
            }
            mlo = fmaxf(mlo, __shfl_xor_sync(0xffffffffu, mlo, 1));
            mlo = fmaxf(mlo, __shfl_xor_sync(0xffffffffu, mlo, 2));
            mhi = fmaxf(mhi, __shfl_xor_sync(0xffffffffu, mhi, 1));
            mhi = fmaxf(mhi, __shfl_xor_sync(0xffffffffu, mhi, 2));

            float slo = 0.0f, shi = 0.0f;
            #pragma unroll
            for (int j = 0; j < 7; j++) {
                sc[i][j][0] = __expf(sc[i][j][0] - mlo);
                sc[i][j][1] = __expf(sc[i][j][1] - mlo);
                sc[i][j][2] = __expf(sc[i][j][2] - mhi);
                sc[i][j][3] = __expf(sc[i][j][3] - mhi);
                slo += sc[i][j][0] + sc[i][j][1];
                shi += sc[i][j][2] + sc[i][j][3];
            }
            slo += __shfl_xor_sync(0xffffffffu, slo, 1);
            slo += __shfl_xor_sync(0xffffffffu, slo, 2);
            shi += __shfl_xor_sync(0xffffffffu, shi, 1);
            shi += __shfl_xor_sync(0xffffffffu, shi, 2);
            invlo[i] = 1.0f / slo;
            invhi[i] = 1.0f / shi;
        }

        // PV: O = P V (C->A via shuffles)
        float oacc[2][2][4];
        #pragma unroll
        for (int i = 0; i < 2; i++)
            #pragma unroll
            for (int jn = 0; jn < 2; jn++)
                #pragma unroll
                for (int r = 0; r < 4; r++) oacc[i][jn][r] = 0.0f;

        const unsigned src0 = (lane & 28) | (qcol >> 1);
        const unsigned src1 = src0 + 2;
        const bool odd = (qcol & 1) != 0;

        #pragma unroll
        for (int kt = 0; kt < 7; kt++) {
            uint32_t Bh[2][2];
            #pragma unroll
            for (int jn = 0; jn < 2; jn++) {
                const float* bp = vt_h + (jn * 8 + qrow) * 60 + kt * 8 + qcol;
                Bh[jn][0] = __float_as_uint(to_tf32(bp[0]));
                Bh[jn][1] = __float_as_uint(to_tf32(bp[4]));
            }
            #pragma unroll
            for (int i = 0; i < 2; i++) {
                float t0 = __shfl_sync(0xffffffffu, sc[i][kt][0], src0);
                float t1 = __shfl_sync(0xffffffffu, sc[i][kt][1], src0);
                float u0 = __shfl_sync(0xffffffffu, sc[i][kt][0], src1);
                float u1 = __shfl_sync(0xffffffffu, sc[i][kt][1], src1);
                float t2 = __shfl_sync(0xffffffffu, sc[i][kt][2], src0);
                float t3 = __shfl_sync(0xffffffffu, sc[i][kt][3], src0);
                float u2 = __shfl_sync(0xffffffffu, sc[i][kt][2], src1);
                float u3 = __shfl_sync(0xffffffffu, sc[i][kt][3], src1);
                const uint32_t Ah0 = __float_as_uint(to_tf32(odd ? t1 : t0));
                const uint32_t Ah1 = __float_as_uint(to_tf32(odd ? t3 : t2));
                const uint32_t Ah2 = __float_as_uint(to_tf32(odd ? u1 : u0));
                const uint32_t Ah3 = __float_as_uint(to_tf32(odd ? u3 : u2));
                #pragma unroll
                for (int jn = 0; jn < 2; jn++)
                    mma_tf32(oacc[i][jn], Ah0, Ah1, Ah2, Ah3, Bh[jn][0], Bh[jn][1]);
            }
        }

        // store (predicated rows < 49), 1/rowsum folded
        #pragma unroll
        for (int i = 0; i < 2; i++) {
            const int it = rowhalf * 2 + i;
            const int rlo = it * 16 + qrow;
            const int rhi = rlo + 8;
            #pragma unroll
            for (int jn = 0; jn < 2; jn++) {
                const int d = jn * 8 + 2 * qcol;
                if (rlo < 49) {
                    float2 v;
                    v.x = oacc[i][jn][0] * invlo[i];
                    v.y = oacc[i][jn][1] * invlo[i];
                    *reinterpret_cast<float2*>(outBase + (size_t)rlo * 128 + d) = v;
                }
                if (rhi < 49) {
                    float2 v;
                    v.x = oacc[i][jn][2] * invhi[i];
                    v.y = oacc[i][jn][3] * invhi[i];
                    *reinterpret_cast<float2*>(outBase + (size_t)rhi * 128 + d) = v;
                }
            }
        }
    }
}

// ---------------------------------------------------------------------------
// K4: out-proj GEMM + window merge (R11's proven kernel, MODE 1 only).
// 64x128 tile, paired-k LDS.64 frag loads, LDA=136, 2 CTAs/SM.
// ---------------------------------------------------------------------------
__global__ void __launch_bounds__(256, 2)
gemm_out_kernel(const float* __restrict__ A,
                const float* __restrict__ WT,      // [128][128] tf32, k-permuted
                const float* __restrict__ bias,
                float* __restrict__ out)
{
    extern __shared__ float sm[];
    float* As = sm;                          // [64][SMEM_LDA]
    float* Bs = sm + 64 * SMEM_LDA;          // [128][SMEM_LDA]

    const int tid  = threadIdx.x;
    const int warp = tid >> 5, lane = tid & 31;
    const int wm = (warp >> 2) * 32;
    const int wn = (warp & 3) * 32;
    const int qrow = lane >> 2;
    const int qcol = lane & 3;
    const int mBase = blockIdx.x * 64;

    const float4* A4 = reinterpret_cast<const float4*>(A);
    const int rot = (lane >> 3) & 3;
    #pragma unroll
    for (int j = 0; j < 8; j++) {
        const int m = warp + 8 * j;
        float4 v = A4[(size_t)(mBase + m) * 32 + lane];
        v.x = to_tf32(v.x); v.y = to_tf32(v.y);
        v.z = to_tf32(v.z); v.w = to_tf32(v.w);
        const float vals[4] = {v.x, v.y, v.z, v.w};
        float* abase = &As[m * SMEM_LDA + (lane >> 1) * 8 + (lane & 1)];
        #pragma unroll
        for (int s = 0; s < 4; s++) {
            const int c = (s + rot) & 3;
            abase[2 * c] = vals[c];
        }
    }

    const float4* W4 = reinterpret_cast<const float4*>(WT);
    #pragma unroll
    for (int i = tid; i < 4096; i += 256) {
        const int n = i >> 5, k4 = i & 31;
        *reinterpret_cast<float4*>(&Bs[n * SMEM_LDA + k4 * 4]) = W4[(size_t)n * 32 + k4];
    }
    __syncthreads();

    const float* aBase = As + (wm + qrow) * SMEM_LDA + 2 * qcol;
    const float* bBase = Bs + (wn + qrow) * SMEM_LDA + 2 * qcol;

    float acc[2][4][4];
    #pragma unroll
    for (int i = 0; i < 2; i++)
        #pragma unroll
        for (int j = 0; j < 4; j++)
            #pragma unroll
            for (int r = 0; r < 4; r++) acc[i][j][r] = 0.0f;

    #pragma unroll
    for (int ks = 0; ks < 16; ks++) {
        const int kk = ks * 8;
        float2 alo[2], ahi[2];
        #pragma unroll
        for (int i = 0; i < 2; i++) {
            alo[i] = *reinterpret_cast<const float2*>(aBase + i * 16 * SMEM_LDA + kk);
            ahi[i] = *reinterpret_cast<const float2*>(aBase + i * 16 * SMEM_LDA + 8 * SMEM_LDA + kk);
        }
        float2 bv[4];
        #pragma unroll
        for (int j = 0; j < 4; j++)
            bv[j] = *reinterpret_cast<const float2*>(bBase + j * 8 * SMEM_LDA + kk);
        #pragma unroll
        for (int i = 0; i < 2; i++)
            #pragma unroll
            for (int j = 0; j < 4; j++)
                mma_tf32(acc[i][j],
                         __float_as_uint(alo[i].x), __float_as_uint(ahi[i].x),
                         __float_as_uint(alo[i].y), __float_as_uint(ahi[i].y),
                         __float_as_uint(bv[j].x),  __float_as_uint(bv[j].y));
    }

    #pragma unroll
    for (int i = 0; i < 2; i++) {
        #pragma unroll
        for (int half = 0; half < 2; half++) {
            const int t = mBase + wm + i * 16 + qrow + half * 8;
            const int g = t / 49, p = t - g * 49;
            const int b = g >> 6, w = g & 63;
            const int row = (w >> 3) * 7 + p / 7;
            const int col = (w & 7) * 7 + p % 7;
            float* op = out + ((size_t)b * 3136 + row * 56 + col) * 128;
            #pragma unroll
            for (int j = 0; j < 4; j++) {
                const int cofs = wn + j * 8 + 2 * qcol;
                float2 v;
                v.x = acc[i][j][half * 2 + 0] + __ldg(&bias[cofs]);
                v.y = acc[i][j][half * 2 + 1] + __ldg(&bias[cofs + 1]);
                *reinterpret_cast<float2*>(op + cofs) = v;
            }
        }
    }
}

// ---------------------------------------------------------------------------
// Launch
// ---------------------------------------------------------------------------
extern "C" void kernel_launch(void* const* d_in, const int* in_sizes, int n_in,
                              void* d_out, int out_size)
{
    const float* x       = (const float*)d_in[0];
    const float* ln_g    = (const float*)d_in[1];
    const float* ln_b    = (const float*)d_in[2];
    const float* w_qkv   = (const float*)d_in[3];
    const float* b_qkv   = (const float*)d_in[4];
    const float* w_out   = (const float*)d_in[5];
    const float* b_out   = (const float*)d_in[6];
    float* out           = (float*)d_out;

    void *xw_ptr = nullptr, *wT_ptr = nullptr;
    cudaGetSymbolAddress(&xw_ptr, g_xw);
    cudaGetSymbolAddress(&wT_ptr, g_wT);
    float* xw = (float*)xw_ptr;
    float* wT = (float*)wT_ptr;

    const int smemG = (64 + 128) * SMEM_LDA * sizeof(float);  // 104448 B
    cudaFuncSetAttribute((const void*)fused_qkv_attn_kernel,
                         cudaFuncAttributeMaxDynamicSharedMemorySize, FUSED_SMEM);
    cudaFuncSetAttribute((const void*)gemm_out_kernel,
                         cudaFuncAttributeMaxDynamicSharedMemorySize, smemG);

    // K0: weight transpose + tf32 round + k-permute (tiny)
    transpose_w_kernel<<<192, 256>>>(w_qkv, w_out, wT);

    // KF: fused LN + window partition + QKV GEMM + attention
    fused_qkv_attn_kernel<<<4096, 256, FUSED_SMEM>>>(x, wT, b_qkv, ln_g, ln_b, xw);

    // K4: out projection + window merge
    gemm_out_kernel<<<NTOK / 64, 256, smemG>>>(xw, wT + 49152, b_out, out);
}